// round 17
// baseline (speedup 1.0000x reference)
#include <cuda_runtime.h>
#include <cuda_fp16.h>
#include <math.h>
#include <stdint.h>

// ---------------- problem constants ----------------
constexpr int Bv = 8, Tv = 8, Hv = 56, Wv = 56, Cv = 192;
constexpr int NHv = 6, Lv = Hv * Wv;                // 3136
constexpr int HIDv = 4 * Cv;                        // 768
constexpr int Mv = Bv * Tv * Lv;                    // 200704 tokens
constexpr long MCl = (long)Mv * Cv;
constexpr float QSCALE = 0.17677669529663687f;      // 32^-0.5

// ---------------- device scratch ----------------
__device__ __half g_qkv[(long)Mv * 576];
__device__ __half g_a[MCl];
__device__ __half g_osp[MCl];
__device__ __half g_ot[MCl];
__device__ __half g_h[(long)Mv * HIDv];
__device__ __half g_cat[(long)Mv * 384];
__device__ __half g_whi[847872];
__device__ float g_xt_fb[MCl];
__device__ float g_xsp_fb[MCl];

// weight offsets
constexpr int WO_QKV = 0;            // 576x192
constexpr int WO_PSP = 110592;       // 192x192
constexpr int WO_PT  = 147456;       // 192x192
constexpr int WO_TF1 = 184320;       // 768x192
constexpr int WO_TF2 = 331776;       // 192x768
constexpr int WO_SF1 = 479232;       // 768x192
constexpr int WO_SF2 = 626688;       // 192x768
constexpr int WO_FUSE = 774144;      // 192x384

// ---------------- helpers ----------------
__device__ __forceinline__ uint32_t smem_u32(const void* p) {
    uint32_t a;
    asm("{ .reg .u64 t; cvta.to.shared.u64 t, %1; cvt.u32.u64 %0, t; }" : "=r"(a) : "l"(p));
    return a;
}
__device__ __forceinline__ uint32_t pack_h2(float x, float y) {
    __half2 h = __floats2half2_rn(x, y);
    return *reinterpret_cast<uint32_t*>(&h);
}

#define LDSM4(r, addr)                                                        \
    asm volatile("ldmatrix.sync.aligned.m8n8.x4.shared.b16 {%0,%1,%2,%3}, [%4];" \
        : "=r"((r)[0]), "=r"((r)[1]), "=r"((r)[2]), "=r"((r)[3]) : "r"(addr))

#define LDSM4T(r, addr)                                                       \
    asm volatile("ldmatrix.sync.aligned.m8n8.x4.trans.shared.b16 {%0,%1,%2,%3}, [%4];" \
        : "=r"((r)[0]), "=r"((r)[1]), "=r"((r)[2]), "=r"((r)[3]) : "r"(addr))

#define MMA_F16(c, a, b0, b1)                                                 \
    asm volatile("mma.sync.aligned.m16n8k16.row.col.f32.f16.f16.f32 "         \
        "{%0,%1,%2,%3},{%4,%5,%6,%7},{%8,%9},{%0,%1,%2,%3};"                  \
        : "+f"((c)[0]), "+f"((c)[1]), "+f"((c)[2]), "+f"((c)[3])              \
        : "r"((a)[0]), "r"((a)[1]), "r"((a)[2]), "r"((a)[3]), "r"(b0), "r"(b1))

#define CP16(smem, gptr)                                                      \
    asm volatile("cp.async.cg.shared.global [%0], [%1], 16;"                  \
        :: "r"(smem), "l"(gptr) : "memory")
#define CP_COMMIT() asm volatile("cp.async.commit_group;" ::: "memory")
#define CP_WAIT2()  asm volatile("cp.async.wait_group 2;" ::: "memory")

// ---------------- fp16 pipelined GEMM: 4 warps, warp tile 64x48, K=32/stage ----
// CTA tile 128x96; smem stage (80B rows): A 0 (128x64B) | W 10240 (96x64B);
// stage 17920, 4-ring (71680 B), 3 CTAs/SM.
constexpr int STAGE = 17920;
constexpr int NSTG = 4;
constexpr int DSMEM = NSTG * STAGE;

template <int KD, int EM>
__global__ void __launch_bounds__(128, 3)
mma_gemm(const __half* __restrict__ A, const __half* __restrict__ W,
         const float* __restrict__ bias, const float* __restrict__ R,
         float* __restrict__ Y, __half* __restrict__ Yh,
         __half* __restrict__ Cat, int catoff, int N) {
    extern __shared__ char sm[];
    const int tid = threadIdx.x;
    const long m0 = (long)blockIdx.x * 128;
    const int n0 = blockIdx.y * 96;
    constexpr int NS = KD / 32;
    const uint32_t smb = smem_u32(sm);

    auto fill = [&](int s) {
        const uint32_t sb = smb + (s % NSTG) * STAGE;
        {
            const char* g = reinterpret_cast<const char*>(A + (m0 + tid) * (long)KD + s * 32);
            uint32_t d = sb + tid * 80;
            CP16(d, g); CP16(d + 16, g + 16); CP16(d + 32, g + 32); CP16(d + 48, g + 48);
        }
        if (tid < 96) {
            const char* g = reinterpret_cast<const char*>(W + (long)(n0 + tid) * KD + s * 32);
            uint32_t d = sb + 10240 + tid * 80;
            CP16(d, g); CP16(d + 16, g + 16); CP16(d + 32, g + 32); CP16(d + 48, g + 48);
        }
    };

    // 4 warps = 2(M) x 2(N); warp tile 64x48
    const int l = tid & 31, wid = tid >> 5;
    const int wm = wid & 1, wn = wid >> 1;
    const int arow = wm * 64 + (l & 15);
    const int acol8 = (l >> 4) * 8;
    const int brow = wn * 48 + (l & 7) + ((l >> 4) << 3);
    const int bcol8 = ((l >> 3) & 1) * 8;

    float acc[4][6][4];
#pragma unroll
    for (int i = 0; i < 4; i++)
#pragma unroll
        for (int j = 0; j < 6; j++)
#pragma unroll
            for (int k = 0; k < 4; k++) acc[i][j][k] = 0.f;

    auto mmastage = [&](int buf) {
        const uint32_t base = smb + buf * STAGE;
#pragma unroll
        for (int kt = 0; kt < 2; kt++) {
            uint32_t af[4][4];
#pragma unroll
            for (int mt = 0; mt < 4; mt++)
                LDSM4(af[mt], base + (arow + mt * 16) * 80 + (kt * 16 + acol8) * 2);
#pragma unroll
            for (int nt = 0; nt < 3; nt++) {
                uint32_t bf[4];
                LDSM4(bf, base + 10240 + (brow + nt * 16) * 80 + (kt * 16 + bcol8) * 2);
#pragma unroll
                for (int mt = 0; mt < 4; mt++)
#pragma unroll
                    for (int jj = 0; jj < 2; jj++)
                        MMA_F16(acc[mt][nt * 2 + jj], af[mt], bf[2 * jj], bf[2 * jj + 1]);
            }
        }
    };

    fill(0); CP_COMMIT();
    fill(1); CP_COMMIT();
    fill(2); CP_COMMIT();
    for (int s = 0; s < NS; s++) {
        CP_WAIT2();
        __syncthreads();
        mmastage(s % NSTG);
        if (s + 3 < NS) fill(s + 3);
        CP_COMMIT();
    }

    const int g = l >> 2, tg = l & 3;
#pragma unroll
    for (int mt = 0; mt < 4; mt++)
#pragma unroll
        for (int nn = 0; nn < 6; nn++) {
            const int col = n0 + wn * 48 + nn * 8 + 2 * tg;
            const float b0 = bias[col], b1 = bias[col + 1];
#pragma unroll
            for (int h = 0; h < 2; h++) {
                const long row = m0 + wm * 64 + mt * 16 + g + 8 * h;
                float vx = acc[mt][nn][2 * h] + b0;
                float vy = acc[mt][nn][2 * h + 1] + b1;
                if (EM == 1) {
                    if (col < 192) { vx *= QSCALE; vy *= QSCALE; }
                    reinterpret_cast<uint32_t*>(Yh)[(row * (long)N + col) >> 1] = pack_h2(vx, vy);
                }
                if (EM == 0) {
                    *reinterpret_cast<float2*>(Y + row * (long)N + col) = make_float2(vx, vy);
                }
                if (EM == 2) {
                    float2 rv = *reinterpret_cast<const float2*>(R + row * (long)N + col);
                    vx += rv.x; vy += rv.y;
                    *reinterpret_cast<float2*>(Y + row * (long)N + col) = make_float2(vx, vy);
                    if (Cat) {
                        reinterpret_cast<uint32_t*>(Cat)[(row * 384 + catoff + col) >> 1] =
                            pack_h2(vx, vy);
                    }
                }
                if (EM == 4) {
                    vx = 0.5f * vx * (1.0f + erff(vx * 0.70710678118654752f));
                    vy = 0.5f * vy * (1.0f + erff(vy * 0.70710678118654752f));
                    reinterpret_cast<uint32_t*>(Yh)[(row * (long)N + col) >> 1] = pack_h2(vx, vy);
                }
            }
        }
}

// ---------------- combined weight preconversion (fp16 single plane) ----------------
__global__ void w_conv_all_kernel(const float* qkv_w, const float* psp_w, const float* pt_w,
                                  const float* tf1_w, const float* tf2_w, const float* sf1_w,
                                  const float* sf2_w, const float* fuse_w,
                                  __half* __restrict__ hi) {
    int i = blockIdx.x * 256 + threadIdx.x;
    if (i >= 847872) return;
    float v;
    if (i < WO_PSP)       v = qkv_w[i - WO_QKV];
    else if (i < WO_PT)   v = psp_w[i - WO_PSP];
    else if (i < WO_TF1)  v = pt_w[i - WO_PT];
    else if (i < WO_TF2)  v = tf1_w[i - WO_TF1];
    else if (i < WO_SF1)  v = tf2_w[i - WO_TF2];
    else if (i < WO_SF2)  v = sf1_w[i - WO_SF1];
    else if (i < WO_FUSE) v = sf2_w[i - WO_SF2];
    else                  v = fuse_w[i - WO_FUSE];
    hi[i] = __float2half_rn(v);
}

// ---------------- LN fused stats+apply -> fp16 ----------------
__global__ void ln_apply_kernel(const float* __restrict__ X,
                                const float* __restrict__ gamma, const float* __restrict__ beta,
                                __half* __restrict__ O) {
    int tok = blockIdx.x * 8 + (threadIdx.x >> 5);
    int lane = threadIdx.x & 31;
    const float* p = X + (long)tok * Cv;
    float v[6];
#pragma unroll
    for (int i = 0; i < 6; i++) v[i] = p[lane + i * 32];
    float s = v[0] + v[1] + v[2] + v[3] + v[4] + v[5];
#pragma unroll
    for (int o = 16; o > 0; o >>= 1) s += __shfl_xor_sync(~0u, s, o);
    float mu = s * (1.0f / Cv);
    float qv = 0.f;
#pragma unroll
    for (int i = 0; i < 6; i++) { float d = v[i] - mu; qv += d * d; }
#pragma unroll
    for (int o = 16; o > 0; o >>= 1) qv += __shfl_xor_sync(~0u, qv, o);
    float rs = rsqrtf(qv * (1.0f / Cv) + 1e-5f);
#pragma unroll
    for (int i = 0; i < 6; i++) {
        int c = lane + i * 32;
        O[(long)tok * Cv + c] = __float2half_rn((v[i] - mu) * rs * gamma[c] + beta[c]);
    }
}

// ---------------- spatial window attention on tensor cores (smem overlay) ----------
// Softmax: 2 threads/row, PAIR-masked shuffles only (no full-warp collectives in
// the diverged region). Each half scales/packs only its own columns.
__global__ void __launch_bounds__(128, 6) attn_spatial_kernel(const __half* __restrict__ qkv,
                                                              __half* __restrict__ O) {
    __shared__ __half QKVs[3][64][40];
    __shared__ float sc[64][57];
    __half (*Qs)[40] = QKVs[0];
    __half (*Ks)[40] = QKVs[1];
    __half (*Vs)[40] = QKVs[2];

    const int gh = blockIdx.x;
    const int g = gh / 6, h = gh % 6;
    const int b = g >> 9;
    const int rem = g & 511;
    const int win = rem >> 3, t = rem & 7;
    const int wh = win >> 3, ww = win & 7;
    const int tid = threadIdx.x;
    const int l = tid & 31, w = tid >> 5;
    const long frame = (long)(b * 8 + t) * Lv;

    for (int z = tid; z < 15 * 20; z += 128)
        reinterpret_cast<uint32_t*>(&Vs[49 + z / 20][0])[z % 20] = 0;

    for (int u = tid; u < 49 * 12; u += 128) {
        const int i = u / 12, c = u % 12;
        const int seg = c >> 2, cc = c & 3;
        const int ltok = (wh * 7 + i / 7) * 56 + ww * 7 + (i % 7);
        const long base = (frame + ltok) * 576 + seg * 192 + h * 32 + cc * 8;
        uint4 v = *reinterpret_cast<const uint4*>(qkv + base);
        *reinterpret_cast<uint4*>(&QKVs[seg][i][cc * 8]) = v;
    }
    __syncthreads();

    const uint32_t q_b = smem_u32(Qs), k_b = smem_u32(Ks), v_b = smem_u32(Vs);
    const uint32_t p_b = q_b;
    __half* Pp = &Qs[0][0];

    // ---- scores ----
    {
        float acc[7][4];
#pragma unroll
        for (int nt = 0; nt < 7; nt++)
#pragma unroll
            for (int k = 0; k < 4; k++) acc[nt][k] = 0.f;

        const int abrow = w * 16 + (l & 15);
        const int bq = (l & 7) + ((l >> 4) << 3);
        const int bk8 = ((l >> 3) & 1) * 8;
#pragma unroll
        for (int kt = 0; kt < 2; kt++) {
            uint32_t af[4];
            LDSM4(af, q_b + abrow * 80 + (kt * 16 + (l >> 4) * 8) * 2);
#pragma unroll
            for (int np = 0; np < 4; np++) {
                uint32_t bf[4];
                LDSM4(bf, k_b + (np * 16 + bq) * 80 + (kt * 16 + bk8) * 2);
                MMA_F16(acc[np * 2], af, bf[0], bf[1]);
                if (np < 3) MMA_F16(acc[np * 2 + 1], af, bf[2], bf[3]);
            }
        }
        const int r0 = w * 16 + (l >> 2), c0 = 2 * (l & 3);
#pragma unroll
        for (int nt = 0; nt < 7; nt++) {
            sc[r0][nt * 8 + c0] = acc[nt][0];
            sc[r0][nt * 8 + c0 + 1] = acc[nt][1];
            sc[r0 + 8][nt * 8 + c0] = acc[nt][2];
            sc[r0 + 8][nt * 8 + c0 + 1] = acc[nt][3];
        }
    }
    __syncthreads();

    // ---- softmax: 2 threads/row, pair-masked shuffles; rows>=49 zero P pads ----
    {
        const int row = tid >> 1, half = tid & 1;
        const unsigned pm = 0x3u << (l & 30);          // this pair's two lanes
        if (row < 49) {
            const int j0 = half ? 24 : 0, jend = half ? 49 : 24;
            float mx = -1e30f;
#pragma unroll 1
            for (int j = j0; j < jend; j++) mx = fmaxf(mx, sc[row][j]);
            mx = fmaxf(mx, __shfl_xor_sync(pm, mx, 1));
            float sum = 0.f;
#pragma unroll 1
            for (int j = j0; j < jend; j++) { float e = __expf(sc[row][j] - mx); sc[row][j] = e; sum += e; }
            sum += __shfl_xor_sync(pm, sum, 1);
            float inv = 1.0f / sum;
            uint32_t* prow = reinterpret_cast<uint32_t*>(Pp + row * 72);
            if (half == 0) {
                // own cols 0..23 -> words 0..11; pad words 25..28
#pragma unroll 1
                for (int jj = 0; jj < 12; jj++)
                    prow[jj] = pack_h2(sc[row][2 * jj] * inv, sc[row][2 * jj + 1] * inv);
#pragma unroll
                for (int jj = 25; jj < 29; jj++) prow[jj] = 0u;
            } else {
                // own cols 24..48 -> words 12..24; pad words 29..31
#pragma unroll 1
                for (int jj = 12; jj < 24; jj++)
                    prow[jj] = pack_h2(sc[row][2 * jj] * inv, sc[row][2 * jj + 1] * inv);
                prow[24] = pack_h2(sc[row][48] * inv, 0.f);
#pragma unroll
                for (int jj = 29; jj < 32; jj++) prow[jj] = 0u;
            }
        } else {
            // zero P pad row (36 words split 18/18); no collectives here
            uint32_t* prow = reinterpret_cast<uint32_t*>(Pp + row * 72);
#pragma unroll
            for (int jj = 0; jj < 18; jj++) prow[half * 18 + jj] = 0u;
        }
    }
    __syncthreads();

    // ---- AV ----
    {
        float acc2[4][4];
#pragma unroll
        for (int nt = 0; nt < 4; nt++)
#pragma unroll
            for (int k = 0; k < 4; k++) acc2[nt][k] = 0.f;

        const int arow = w * 16 + (l & 15);
#pragma unroll
        for (int kt = 0; kt < 4; kt++) {
            uint32_t af[4];
            LDSM4(af, p_b + arow * 144 + (kt * 16 + (l >> 4) * 8) * 2);
#pragma unroll
            for (int np = 0; np < 2; np++) {
                uint32_t bt[4];
                LDSM4T(bt, v_b + (kt * 16 + (l & 15)) * 80 + (np * 16 + ((l >> 4) & 1) * 8) * 2);
                MMA_F16(acc2[np * 2], af, bt[0], bt[1]);
                MMA_F16(acc2[np * 2 + 1], af, bt[2], bt[3]);
            }
        }
        const int r0 = w * 16 + (l >> 2), c0 = 2 * (l & 3);
#pragma unroll
        for (int half = 0; half < 2; half++) {
            const int i = r0 + half * 8;
            if (i < 49) {
                const int ltok = (wh * 7 + i / 7) * 56 + ww * 7 + (i % 7);
                const long base = (frame + ltok) * 192 + h * 32;
#pragma unroll
                for (int nt = 0; nt < 4; nt++)
                    reinterpret_cast<uint32_t*>(O + base + nt * 8 + c0)[0] =
                        pack_h2(acc2[nt][2 * half], acc2[nt][2 * half + 1]);
            }
        }
    }
}

// ---------------- temporal attention: half2, 2 heads per warp ----------------
__global__ void __launch_bounds__(256) attn_temporal_kernel(const __half* __restrict__ qkv,
                                                            __half* __restrict__ O) {
    const int unit = blockIdx.x * 8 + (threadIdx.x >> 5);
    const int lane = threadIdx.x & 31;
    const int g = unit / 3, hp = unit % 3;
    const int b = g / Lv, l = g % Lv;
    const int head = hp * 2 + (lane >> 4);
    const int ch = (lane & 15) * 2;
    const long base0 = ((long)(b * 8) * Lv + l) * 576 + head * 32 + ch;
    const long tstride = (long)Lv * 576;

    float2 q[8], k[8], v[8];
#pragma unroll
    for (int t = 0; t < 8; t++) {
        long base = base0 + (long)t * tstride;
        q[t] = __half22float2(*reinterpret_cast<const __half2*>(qkv + base));
        k[t] = __half22float2(*reinterpret_cast<const __half2*>(qkv + base + 192));
        v[t] = __half22float2(*reinterpret_cast<const __half2*>(qkv + base + 384));
    }
#pragma unroll
    for (int t1 = 0; t1 < 8; t1++) {
        float s[8];
#pragma unroll
        for (int t2 = 0; t2 < 8; t2++) s[t2] = q[t1].x * k[t2].x + q[t1].y * k[t2].y;
#pragma unroll
        for (int o = 8; o > 0; o >>= 1) {
#pragma unroll
            for (int t2 = 0; t2 < 8; t2++) s[t2] += __shfl_xor_sync(~0u, s[t2], o);
        }
        float mx = s[0];
#pragma unroll
        for (int t2 = 1; t2 < 8; t2++) mx = fmaxf(mx, s[t2]);
        float sum = 0.f;
#pragma unroll
        for (int t2 = 0; t2 < 8; t2++) { s[t2] = __expf(s[t2] - mx); sum += s[t2]; }
        float inv = 1.0f / sum;
        float ox = 0.f, oy = 0.f;
#pragma unroll
        for (int t2 = 0; t2 < 8; t2++) { ox += s[t2] * v[t2].x; oy += s[t2] * v[t2].y; }
        long e = ((long)(b * 8 + t1) * Lv + l) * 192 + head * 32 + ch;
        reinterpret_cast<uint32_t*>(O + e)[0] = pack_h2(ox * inv, oy * inv);
    }
}

// ---------------- launcher ----------------
extern "C" void kernel_launch(void* const* d_in, const int* in_sizes, int n_in,
                              void* d_out, int out_size) {
    (void)in_sizes; (void)n_in;
    const float* x        = (const float*)d_in[0];
    const float* norm1_g  = (const float*)d_in[2];
    const float* norm1_b  = (const float*)d_in[3];
    const float* qkv_w    = (const float*)d_in[4];
    const float* qkv_b    = (const float*)d_in[5];
    const float* proj_sp_w = (const float*)d_in[6];
    const float* proj_sp_b = (const float*)d_in[7];
    const float* proj_t_w = (const float*)d_in[8];
    const float* proj_t_b = (const float*)d_in[9];
    const float* norm2_g  = (const float*)d_in[10];
    const float* norm2_b  = (const float*)d_in[11];
    const float* te_fc1_w = (const float*)d_in[12];
    const float* te_fc1_b = (const float*)d_in[13];
    const float* te_fc2_w = (const float*)d_in[14];
    const float* te_fc2_b = (const float*)d_in[15];
    const float* sp_fc1_w = (const float*)d_in[16];
    const float* sp_fc1_b = (const float*)d_in[17];
    const float* sp_fc2_w = (const float*)d_in[18];
    const float* sp_fc2_b = (const float*)d_in[19];
    const float* fuse_w   = (const float*)d_in[20];
    const float* fuse_b   = (const float*)d_in[21];

    float* out = (float*)d_out;
    float *xt, *xsp;
    if ((long)out_size >= 3 * MCl) {
        xt = out + MCl;
        xsp = out + 2 * MCl;
    } else {
        void* p;
        cudaGetSymbolAddress(&p, g_xt_fb);  xt = (float*)p;
        cudaGetSymbolAddress(&p, g_xsp_fb); xsp = (float*)p;
    }
    void* p;
    cudaGetSymbolAddress(&p, g_qkv);  __half* qkv = (__half*)p;
    cudaGetSymbolAddress(&p, g_a);    __half* a = (__half*)p;
    cudaGetSymbolAddress(&p, g_osp);  __half* osp = (__half*)p;
    cudaGetSymbolAddress(&p, g_ot);   __half* ot = (__half*)p;
    cudaGetSymbolAddress(&p, g_h);    __half* hb = (__half*)p;
    cudaGetSymbolAddress(&p, g_cat);  __half* cat = (__half*)p;
    cudaGetSymbolAddress(&p, g_whi);  __half* whi = (__half*)p;

    cudaFuncSetAttribute(mma_gemm<192, 1>, cudaFuncAttributeMaxDynamicSharedMemorySize, DSMEM);
    cudaFuncSetAttribute(mma_gemm<192, 2>, cudaFuncAttributeMaxDynamicSharedMemorySize, DSMEM);
    cudaFuncSetAttribute(mma_gemm<192, 4>, cudaFuncAttributeMaxDynamicSharedMemorySize, DSMEM);
    cudaFuncSetAttribute(mma_gemm<768, 2>, cudaFuncAttributeMaxDynamicSharedMemorySize, DSMEM);
    cudaFuncSetAttribute(mma_gemm<384, 0>, cudaFuncAttributeMaxDynamicSharedMemorySize, DSMEM);

    const int MT = Mv / 128;  // 1568

    w_conv_all_kernel<<<(847872 + 255) / 256, 256>>>(
        qkv_w, proj_sp_w, proj_t_w, te_fc1_w, te_fc2_w, sp_fc1_w, sp_fc2_w, fuse_w, whi);
    ln_apply_kernel<<<Mv / 8, 256>>>(x, norm1_g, norm1_b, a);
    // QKV (N=576) -> fp16
    mma_gemm<192, 1><<<dim3(MT, 6), 128, DSMEM>>>(
        a, whi + WO_QKV, qkv_b, nullptr, nullptr, qkv, nullptr, 0, 576);
    // attention
    attn_spatial_kernel<<<4096 * 6, 128>>>(qkv, osp);
    attn_temporal_kernel<<<(Bv * Lv * 3) / 8, 256>>>(qkv, ot);
    // proj + residual
    mma_gemm<192, 2><<<dim3(MT, 2), 128, DSMEM>>>(
        osp, whi + WO_PSP, proj_sp_b, x, xsp, nullptr, nullptr, 0, 192);
    mma_gemm<192, 2><<<dim3(MT, 2), 128, DSMEM>>>(
        ot, whi + WO_PT, proj_t_b, x, xt, nullptr, nullptr, 0, 192);
    // temporal MLP (fc2 also emits concat slot 0)
    ln_apply_kernel<<<Mv / 8, 256>>>(xt, norm2_g, norm2_b, a);
    mma_gemm<192, 4><<<dim3(MT, 8), 128, DSMEM>>>(
        a, whi + WO_TF1, te_fc1_b, nullptr, nullptr, hb, nullptr, 0, HIDv);
    mma_gemm<768, 2><<<dim3(MT, 2), 128, DSMEM>>>(
        hb, whi + WO_TF2, te_fc2_b, xt, xt, nullptr, cat, 0, 192);
    // spatial MLP (fc2 emits concat slot 192)
    ln_apply_kernel<<<Mv / 8, 256>>>(xsp, norm2_g, norm2_b, a);
    mma_gemm<192, 4><<<dim3(MT, 8), 128, DSMEM>>>(
        a, whi + WO_SF1, sp_fc1_b, nullptr, nullptr, hb, nullptr, 0, HIDv);
    mma_gemm<768, 2><<<dim3(MT, 2), 128, DSMEM>>>(
        hb, whi + WO_SF2, sp_fc2_b, xsp, xsp, nullptr, cat, 192, 192);
    // fuse
    mma_gemm<384, 0><<<dim3(MT, 2), 128, DSMEM>>>(
        cat, whi + WO_FUSE, fuse_b, nullptr, out, nullptr, nullptr, 0, 192);
}